// round 15
// baseline (speedup 1.0000x reference)
#include <cuda_runtime.h>
#include <cuda_bf16.h>
#include <cuda_fp16.h>
#include <cstdint>

#define NMAX 50048
#define EMAX 1000000
#define FD 128     // H*F_OUT == F_IN == 128
#define HH 8       // heads
#define SB 1024    // scan block size
#define TMR 128    // gemm rows per block
#define SXW 68     // padded sX row stride in words (bank = 4g+t, conflict-free)

// Scratch (static __device__ — no allocations allowed)
__device__ unsigned g_xph[(size_t)NMAX * 64];   // xp as fp16x2 [N][64 words]
__device__ float g_asrc[(size_t)NMAX * HH];
__device__ float g_adst[(size_t)NMAX * HH];
__device__ int   g_cnt[NMAX + 1];
__device__ int   g_rowstart[NMAX + 1];
__device__ int   g_cursor[NMAX];
__device__ int   g_bsum[64];
__device__ int   g_csr[EMAX];
// Pre-packed W fragments for mma.m16n8k16 (kc 0..7, nt 0..15, lane 0..31)
__device__ uint2 g_wbhi[8 * 16 * 32];
__device__ uint2 g_wblo[8 * 16 * 32];

__device__ __forceinline__ void mma16816(float* c, const unsigned* a, uint2 b) {
    asm volatile("mma.sync.aligned.m16n8k16.row.col.f32.bf16.bf16.f32 "
                 "{%0,%1,%2,%3}, {%4,%5,%6,%7}, {%8,%9}, {%0,%1,%2,%3};"
                 : "+f"(c[0]), "+f"(c[1]), "+f"(c[2]), "+f"(c[3])
                 : "r"(a[0]), "r"(a[1]), "r"(a[2]), "r"(a[3]),
                   "r"(b.x), "r"(b.y));
}
__device__ __forceinline__ unsigned bf2_hi(float x, float y, float2& back) {
    __nv_bfloat162 h = __floats2bfloat162_rn(x, y);
    back = __bfloat1622float2(h);
    return *(unsigned*)&h;
}
__device__ __forceinline__ unsigned bf2_pack(float x, float y) {
    __nv_bfloat162 h = __floats2bfloat162_rn(x, y);
    return *(unsigned*)&h;
}
__device__ __forceinline__ unsigned h2_pack(float x, float y) {
    __half2 h = __floats2half2_rn(x, y);
    return *(unsigned*)&h;
}
__device__ __forceinline__ float2 h2_unpack(unsigned u) {
    return __half22float2(*(__half2*)&u);
}

// ---------------------------------------------------------------------------
// Prep: pack W into per-lane mma fragments, split bf16 hi + residual lo.
// ---------------------------------------------------------------------------
__global__ void wfrag_prep(const float* __restrict__ W) {
    int idx = blockIdx.x * blockDim.x + threadIdx.x;   // 0..4095
    if (idx >= 8 * 16 * 32) return;
    int lane = idx & 31;
    int nt   = (idx >> 5) & 15;
    int kc   = idx >> 9;
    int g = lane >> 2, t = lane & 3;
    int nn = nt * 8 + g;
    int k0 = kc * 16 + t * 2;
    float w00 = W[(size_t)k0 * FD + nn];
    float w01 = W[(size_t)(k0 + 1) * FD + nn];
    float w10 = W[(size_t)(k0 + 8) * FD + nn];
    float w11 = W[(size_t)(k0 + 9) * FD + nn];
    float2 f0, f1;
    unsigned h0 = bf2_hi(w00, w01, f0);
    unsigned h1 = bf2_hi(w10, w11, f1);
    g_wbhi[idx] = make_uint2(h0, h1);
    g_wblo[idx] = make_uint2(bf2_pack(w00 - f0.x, w01 - f0.y),
                             bf2_pack(w10 - f1.x, w11 - f1.y));
}

// ---------------------------------------------------------------------------
// Tensor-core GEMM via baseline mma.sync bf16 split precision:
// xp = x @ W = hi@Whi + hi@Wlo + lo@Whi (fp32 accumulate).
// Epilogue stores xp as fp16x2 and computes logits PROGRESSIVELY per head
// (kills the 32-reg logit arrays that pushed the kernel to 106 regs / 22% occ).
// ---------------------------------------------------------------------------
__global__ __launch_bounds__(256) void gemm_mma(
        const float* __restrict__ x,
        const float* __restrict__ att_src,
        const float* __restrict__ att_dst,
        int n) {
    __shared__ unsigned sXhi[TMR * SXW];   // bf16x2 pairs, [row][k2]
    __shared__ unsigned sXlo[TMR * SXW];
    __shared__ float s_att[256];

    const int tid  = threadIdx.x;
    const int w    = tid >> 5;
    const int lane = tid & 31;
    const int g = lane >> 2, t = lane & 3;
    const int row0 = blockIdx.x * TMR;

    {
        const float4* x4 = (const float4*)x;
#pragma unroll
        for (int i = 0; i < 16; i++) {
            int idx = tid + 256 * i;              // 0..4095
            int r  = idx >> 5;
            int c4 = idx & 31;
            float4 v = make_float4(0.f, 0.f, 0.f, 0.f);
            if (row0 + r < n) v = x4[(size_t)(row0 + r) * 32 + c4];
            float2 f01, f23;
            unsigned h01 = bf2_hi(v.x, v.y, f01);
            unsigned h23 = bf2_hi(v.z, v.w, f23);
            *(uint2*)&sXhi[r * SXW + c4 * 2] = make_uint2(h01, h23);
            *(uint2*)&sXlo[r * SXW + c4 * 2] =
                make_uint2(bf2_pack(v.x - f01.x, v.y - f01.y),
                           bf2_pack(v.z - f23.x, v.w - f23.y));
        }
        s_att[tid] = (tid < 128) ? att_src[tid] : att_dst[tid - 128];
    }
    __syncthreads();

    float acc[16][4];
#pragma unroll
    for (int nt = 0; nt < 16; nt++)
#pragma unroll
        for (int j = 0; j < 4; j++) acc[nt][j] = 0.f;

    const int wr = w * 16;
    const int rA = (wr + g) * SXW;
    const int rB = (wr + g + 8) * SXW;
#pragma unroll
    for (int kc = 0; kc < 8; kc++) {
        const int p0 = kc * 8 + t;
        const int p1 = p0 + 4;
        unsigned ahi[4], alo[4];
        ahi[0] = sXhi[rA + p0]; ahi[1] = sXhi[rB + p0];
        ahi[2] = sXhi[rA + p1]; ahi[3] = sXhi[rB + p1];
        alo[0] = sXlo[rA + p0]; alo[1] = sXlo[rB + p0];
        alo[2] = sXlo[rA + p1]; alo[3] = sXlo[rB + p1];

        const uint2* __restrict__ bh = &g_wbhi[kc * 512 + lane];
        const uint2* __restrict__ bl = &g_wblo[kc * 512 + lane];
#pragma unroll
        for (int nt = 0; nt < 16; nt++) {
            uint2 bhv = bh[nt * 32];
            uint2 blv = bl[nt * 32];
            mma16816(acc[nt], ahi, bhv);
            mma16816(acc[nt], alo, bhv);
            mma16816(acc[nt], ahi, blv);
        }
    }

    // Epilogue. Rows r0 = row0+wr+g, r1 = r0+8; lane covers cols nt*8+2t, +1.
    const int r0 = row0 + wr + g;
    const int r1 = r0 + 8;
    const bool ok0 = r0 < n, ok1 = r1 < n;

    // xp stores (fp16x2 word index nt*4+t in the 64-word row)
#pragma unroll
    for (int nt = 0; nt < 16; nt++) {
        if (ok0) g_xph[(size_t)r0 * 64 + nt * 4 + t] = h2_pack(acc[nt][0], acc[nt][1]);
        if (ok1) g_xph[(size_t)r1 * 64 + nt * 4 + t] = h2_pack(acc[nt][2], acc[nt][3]);
    }

    // Logits, one head at a time (head h covers nt = 2h, 2h+1).
#pragma unroll
    for (int h = 0; h < HH; h++) {
        int c0 = (2 * h) * 8 + t * 2;
        int c1 = (2 * h + 1) * 8 + t * 2;
        float as00 = s_att[c0], as01 = s_att[c0 + 1];
        float as10 = s_att[c1], as11 = s_att[c1 + 1];
        float ad00 = s_att[128 + c0], ad01 = s_att[128 + c0 + 1];
        float ad10 = s_att[128 + c1], ad11 = s_att[128 + c1 + 1];
        float vs0 = acc[2*h][0] * as00 + acc[2*h][1] * as01
                  + acc[2*h+1][0] * as10 + acc[2*h+1][1] * as11;
        float vd0 = acc[2*h][0] * ad00 + acc[2*h][1] * ad01
                  + acc[2*h+1][0] * ad10 + acc[2*h+1][1] * ad11;
        float vs1 = acc[2*h][2] * as00 + acc[2*h][3] * as01
                  + acc[2*h+1][2] * as10 + acc[2*h+1][3] * as11;
        float vd1 = acc[2*h][2] * ad00 + acc[2*h][3] * ad01
                  + acc[2*h+1][2] * ad10 + acc[2*h+1][3] * ad11;
        vs0 += __shfl_xor_sync(0xffffffffu, vs0, 1);
        vs0 += __shfl_xor_sync(0xffffffffu, vs0, 2);
        vd0 += __shfl_xor_sync(0xffffffffu, vd0, 1);
        vd0 += __shfl_xor_sync(0xffffffffu, vd0, 2);
        vs1 += __shfl_xor_sync(0xffffffffu, vs1, 1);
        vs1 += __shfl_xor_sync(0xffffffffu, vs1, 2);
        vd1 += __shfl_xor_sync(0xffffffffu, vd1, 1);
        vd1 += __shfl_xor_sync(0xffffffffu, vd1, 2);
        if (t == 0) {
            if (ok0) {
                g_asrc[(size_t)r0 * HH + h] = vs0;
                g_adst[(size_t)r0 * HH + h] = vd0;
            }
            if (ok1) {
                g_asrc[(size_t)r1 * HH + h] = vs1;
                g_adst[(size_t)r1 * HH + h] = vd1;
            }
        }
    }
}

// ---------------------------------------------------------------------------
// CSR build
// ---------------------------------------------------------------------------
__global__ void zerocnt_kernel(int n) {
    int i = blockIdx.x * blockDim.x + threadIdx.x;
    if (i <= n) g_cnt[i] = 0;
}

__global__ void hist_kernel(const int* __restrict__ ei, int E) {
    int t = blockIdx.x * blockDim.x + threadIdx.x;
    int e = t * 4;
    if (e + 3 < E) {
        int4 d = *(const int4*)&ei[E + e];
        atomicAdd(&g_cnt[d.x], 1);
        atomicAdd(&g_cnt[d.y], 1);
        atomicAdd(&g_cnt[d.z], 1);
        atomicAdd(&g_cnt[d.w], 1);
    } else {
        for (int k = e; k < E && k < e + 4; k++)
            atomicAdd(&g_cnt[ei[E + k]], 1);
    }
}

__global__ void scan1_kernel(int n) {
    const int i = blockIdx.x * SB + threadIdx.x;
    const int lane = threadIdx.x & 31, wid = threadIdx.x >> 5;
    int v = (i < n) ? g_cnt[i] : 0;
    int x = v;
#pragma unroll
    for (int off = 1; off < 32; off <<= 1) {
        int y = __shfl_up_sync(0xffffffffu, x, off);
        if (lane >= off) x += y;
    }
    __shared__ int ws[32];
    if (lane == 31) ws[wid] = x;
    __syncthreads();
    if (wid == 0) {
        int s = ws[lane];
#pragma unroll
        for (int off = 1; off < 32; off <<= 1) {
            int y = __shfl_up_sync(0xffffffffu, s, off);
            if (lane >= off) s += y;
        }
        ws[lane] = s;
    }
    __syncthreads();
    int excl = x - v + (wid ? ws[wid - 1] : 0);
    if (i <= n) g_rowstart[i] = excl;
    if (threadIdx.x == SB - 1) g_bsum[blockIdx.x] = excl + v;
}

__global__ void scan2_kernel(int nb) {
    const int lane = threadIdx.x;
    int v0 = (lane < nb) ? g_bsum[lane] : 0;
    int v1 = (lane + 32 < nb) ? g_bsum[lane + 32] : 0;
    int x0 = v0;
#pragma unroll
    for (int off = 1; off < 32; off <<= 1) {
        int y = __shfl_up_sync(0xffffffffu, x0, off);
        if (lane >= off) x0 += y;
    }
    int tot0 = __shfl_sync(0xffffffffu, x0, 31);
    int x1 = v1;
#pragma unroll
    for (int off = 1; off < 32; off <<= 1) {
        int y = __shfl_up_sync(0xffffffffu, x1, off);
        if (lane >= off) x1 += y;
    }
    if (lane < nb)      g_bsum[lane]      = x0 - v0;
    if (lane + 32 < nb) g_bsum[lane + 32] = tot0 + x1 - v1;
}

__global__ void scan3_kernel(int n) {
    int i = blockIdx.x * SB + threadIdx.x;
    if (i <= n) {
        int v = g_rowstart[i] + g_bsum[blockIdx.x];
        g_rowstart[i] = v;
        if (i < n) g_cursor[i] = v;
    }
}

__global__ void scatter_kernel(const int* __restrict__ ei, int E) {
    int t = blockIdx.x * blockDim.x + threadIdx.x;
    int e = t * 4;
    if (e + 3 < E) {
        int4 s = *(const int4*)&ei[e];
        int4 d = *(const int4*)&ei[E + e];
        int p0 = atomicAdd(&g_cursor[d.x], 1);
        int p1 = atomicAdd(&g_cursor[d.y], 1);
        int p2 = atomicAdd(&g_cursor[d.z], 1);
        int p3 = atomicAdd(&g_cursor[d.w], 1);
        g_csr[p0] = s.x;
        g_csr[p1] = s.y;
        g_csr[p2] = s.z;
        g_csr[p3] = s.w;
    } else {
        for (int k = e; k < E && k < e + 4; k++) {
            int d = ei[E + k];
            int p = atomicAdd(&g_cursor[d], 1);
            g_csr[p] = ei[k];
        }
    }
}

// ---------------------------------------------------------------------------
// Fused aggregate + softmax-normalize + bias + LayerNorm.
// One warp per destination node; lane l owns features [4l,4l+4) as fp16x2.
// 4-way edge unroll: 4 independent gather chains in flight (the kernel is
// latency-bound, not bandwidth-bound — R14 lesson).
// ---------------------------------------------------------------------------
__global__ void agg_kernel(const float* __restrict__ bias,
                           const float* __restrict__ gamma,
                           const float* __restrict__ beta,
                           float* __restrict__ out, int n) {
    const int wrp = (blockIdx.x * blockDim.x + threadIdx.x) >> 5;
    if (wrp >= n) return;
    const int lane = threadIdx.x & 31;
    const int h = lane >> 2;

    const int row = g_rowstart[wrp];
    const int end = g_rowstart[wrp + 1];
    const float adh = g_adst[(size_t)wrp * HH + h];
    const uint2* __restrict__ xph = (const uint2*)g_xph;   // row stride 32

    float4 acc = make_float4(0.f, 0.f, 0.f, 0.f);
    float wsum = 0.f;

    int i = row;
    for (; i + 3 < end; i += 4) {
        int s0 = g_csr[i];
        int s1 = g_csr[i + 1];
        int s2 = g_csr[i + 2];
        int s3 = g_csr[i + 3];
        float a0 = g_asrc[(size_t)s0 * HH + h];
        float a1 = g_asrc[(size_t)s1 * HH + h];
        float a2 = g_asrc[(size_t)s2 * HH + h];
        float a3 = g_asrc[(size_t)s3 * HH + h];
        uint2 q0 = xph[(size_t)s0 * 32 + lane];
        uint2 q1 = xph[(size_t)s1 * 32 + lane];
        uint2 q2 = xph[(size_t)s2 * 32 + lane];
        uint2 q3 = xph[(size_t)s3 * 32 + lane];
        float v0 = a0 + adh; v0 = v0 > 0.f ? v0 : 0.2f * v0;
        float v1 = a1 + adh; v1 = v1 > 0.f ? v1 : 0.2f * v1;
        float v2 = a2 + adh; v2 = v2 > 0.f ? v2 : 0.2f * v2;
        float v3 = a3 + adh; v3 = v3 > 0.f ? v3 : 0.2f * v3;
        float w0 = __expf(v0), w1 = __expf(v1);
        float w2 = __expf(v2), w3 = __expf(v3);
        float2 xa, xb;
        xa = h2_unpack(q0.x); xb = h2_unpack(q0.y);
        acc.x = fmaf(w0, xa.x, acc.x); acc.y = fmaf(w0, xa.y, acc.y);
        acc.z = fmaf(w0, xb.x, acc.z); acc.w = fmaf(w0, xb.y, acc.w);
        xa = h2_unpack(q1.x); xb = h2_unpack(q1.y);
        acc.x = fmaf(w1, xa.x, acc.x); acc.y = fmaf(w1, xa.y, acc.y);
        acc.z = fmaf(w1, xb.x, acc.z); acc.w = fmaf(w1, xb.y, acc.w);
        xa = h2_unpack(q2.x); xb = h2_unpack(q2.y);
        acc.x = fmaf(w2, xa.x, acc.x); acc.y = fmaf(w2, xa.y, acc.y);
        acc.z = fmaf(w2, xb.x, acc.z); acc.w = fmaf(w2, xb.y, acc.w);
        xa = h2_unpack(q3.x); xb = h2_unpack(q3.y);
        acc.x = fmaf(w3, xa.x, acc.x); acc.y = fmaf(w3, xa.y, acc.y);
        acc.z = fmaf(w3, xb.x, acc.z); acc.w = fmaf(w3, xb.y, acc.w);
        wsum += (w0 + w1) + (w2 + w3);
    }
    for (; i < end; i++) {
        int s = g_csr[i];
        float v = g_asrc[(size_t)s * HH + h] + adh;
        v = v > 0.f ? v : 0.2f * v;
        float wgt = __expf(v);
        uint2 q = xph[(size_t)s * 32 + lane];
        float2 xa = h2_unpack(q.x), xb = h2_unpack(q.y);
        acc.x = fmaf(wgt, xa.x, acc.x); acc.y = fmaf(wgt, xa.y, acc.y);
        acc.z = fmaf(wgt, xb.x, acc.z); acc.w = fmaf(wgt, xb.y, acc.w);
        wsum += wgt;
    }
    // self loop
    {
        float v = g_asrc[(size_t)wrp * HH + h] + adh;
        v = v > 0.f ? v : 0.2f * v;
        float wgt = __expf(v);
        uint2 q = xph[(size_t)wrp * 32 + lane];
        float2 xa = h2_unpack(q.x), xb = h2_unpack(q.y);
        acc.x = fmaf(wgt, xa.x, acc.x); acc.y = fmaf(wgt, xa.y, acc.y);
        acc.z = fmaf(wgt, xb.x, acc.z); acc.w = fmaf(wgt, xb.y, acc.w);
        wsum += wgt;
    }

    const float inv_w = 1.f / wsum;
    float4 b4 = ((const float4*)bias)[lane];
    float4 o;
    o.x = acc.x * inv_w + b4.x;
    o.y = acc.y * inv_w + b4.y;
    o.z = acc.z * inv_w + b4.z;
    o.w = acc.w * inv_w + b4.w;

    float s1 = o.x + o.y + o.z + o.w;
    float s2 = o.x * o.x + o.y * o.y + o.z * o.z + o.w * o.w;
#pragma unroll
    for (int off = 16; off; off >>= 1) {
        s1 += __shfl_xor_sync(0xffffffffu, s1, off);
        s2 += __shfl_xor_sync(0xffffffffu, s2, off);
    }
    float mu  = s1 * (1.f / 128.f);
    float var = s2 * (1.f / 128.f) - mu * mu;
    float inv = rsqrtf(var + 1e-5f);

    float4 g4 = ((const float4*)gamma)[lane];
    float4 e4 = ((const float4*)beta)[lane];
    float4 r;
    r.x = (o.x - mu) * inv * g4.x + e4.x;
    r.y = (o.y - mu) * inv * g4.y + e4.y;
    r.z = (o.z - mu) * inv * g4.z + e4.z;
    r.w = (o.w - mu) * inv * g4.w + e4.w;
    ((float4*)out)[(size_t)wrp * 32 + lane] = r;
}

// ---------------------------------------------------------------------------
extern "C" void kernel_launch(void* const* d_in, const int* in_sizes, int n_in,
                              void* d_out, int out_size) {
    const float* x       = (const float*)d_in[0];
    const int*   ei      = (const int*)d_in[1];
    const float* W       = (const float*)d_in[2];
    const float* att_src = (const float*)d_in[3];
    const float* att_dst = (const float*)d_in[4];
    const float* bias    = (const float*)d_in[5];
    const float* gamma   = (const float*)d_in[6];
    const float* beta    = (const float*)d_in[7];
    float* out = (float*)d_out;

    const int n = in_sizes[0] / FD;   // 50000
    const int E = in_sizes[1] / 2;    // 800000
    const int nb = (n + 1 + SB - 1) / SB;

    wfrag_prep<<<16, 256>>>(W);                                       // 0
    zerocnt_kernel<<<(n + 1 + 255) / 256, 256>>>(n);                  // 1
    hist_kernel<<<((E + 3) / 4 + 255) / 256, 256>>>(ei, E);           // 2
    gemm_mma<<<(n + TMR - 1) / TMR, 256>>>(x, att_src, att_dst, n);   // 3 (profiler slot)
    scan1_kernel<<<nb, SB>>>(n);                                      // 4
    scan2_kernel<<<1, 32>>>(nb);                                      // 5
    scan3_kernel<<<nb, SB>>>(n);                                      // 6
    scatter_kernel<<<((E + 3) / 4 + 255) / 256, 256>>>(ei, E);        // 7
    agg_kernel<<<(n * 32 + 255) / 256, 256>>>(bias, gamma, beta, out, n); // 8
}

// round 16
// speedup vs baseline: 1.1085x; 1.1085x over previous
#include <cuda_runtime.h>
#include <cuda_bf16.h>
#include <cuda_fp16.h>
#include <cstdint>

#define NMAX 50048
#define EMAX 1000000
#define FD 128     // H*F_OUT == F_IN == 128
#define HH 8       // heads
#define SB 1024    // scan block size
#define TMR 128    // gemm rows per block
#define NTB 8      // n-tiles per block (64 cols; grid.y = 2)
#define SXW 68     // padded sX row stride in words (bank = 4g+t, conflict-free)

// Scratch (static __device__ — no allocations allowed)
__device__ unsigned g_xph[(size_t)NMAX * 64];   // xp as fp16x2 [N][64 words]
__device__ float g_asrc[(size_t)NMAX * HH];
__device__ float g_adst[(size_t)NMAX * HH];
__device__ int   g_cnt[NMAX + 1];
__device__ int   g_rowstart[NMAX + 1];
__device__ int   g_cursor[NMAX];
__device__ int   g_bsum[64];
__device__ int   g_csr[EMAX];
// Pre-packed W fragments for mma.m16n8k16 (kc 0..7, nt 0..15, lane 0..31)
__device__ uint2 g_wbhi[8 * 16 * 32];
__device__ uint2 g_wblo[8 * 16 * 32];

__device__ __forceinline__ void mma16816(float* c, const unsigned* a, uint2 b) {
    asm volatile("mma.sync.aligned.m16n8k16.row.col.f32.bf16.bf16.f32 "
                 "{%0,%1,%2,%3}, {%4,%5,%6,%7}, {%8,%9}, {%0,%1,%2,%3};"
                 : "+f"(c[0]), "+f"(c[1]), "+f"(c[2]), "+f"(c[3])
                 : "r"(a[0]), "r"(a[1]), "r"(a[2]), "r"(a[3]),
                   "r"(b.x), "r"(b.y));
}
__device__ __forceinline__ unsigned bf2_hi(float x, float y, float2& back) {
    __nv_bfloat162 h = __floats2bfloat162_rn(x, y);
    back = __bfloat1622float2(h);
    return *(unsigned*)&h;
}
__device__ __forceinline__ unsigned bf2_pack(float x, float y) {
    __nv_bfloat162 h = __floats2bfloat162_rn(x, y);
    return *(unsigned*)&h;
}
__device__ __forceinline__ unsigned h2_pack(float x, float y) {
    __half2 h = __floats2half2_rn(x, y);
    return *(unsigned*)&h;
}
__device__ __forceinline__ float2 h2_unpack(unsigned u) {
    return __half22float2(*(__half2*)&u);
}

// ---------------------------------------------------------------------------
// Prep: pack W into per-lane mma fragments, split bf16 hi + residual lo.
// ---------------------------------------------------------------------------
__global__ void wfrag_prep(const float* __restrict__ W) {
    int idx = blockIdx.x * blockDim.x + threadIdx.x;   // 0..4095
    if (idx >= 8 * 16 * 32) return;
    int lane = idx & 31;
    int nt   = (idx >> 5) & 15;
    int kc   = idx >> 9;
    int g = lane >> 2, t = lane & 3;
    int nn = nt * 8 + g;
    int k0 = kc * 16 + t * 2;
    float w00 = W[(size_t)k0 * FD + nn];
    float w01 = W[(size_t)(k0 + 1) * FD + nn];
    float w10 = W[(size_t)(k0 + 8) * FD + nn];
    float w11 = W[(size_t)(k0 + 9) * FD + nn];
    float2 f0, f1;
    unsigned h0 = bf2_hi(w00, w01, f0);
    unsigned h1 = bf2_hi(w10, w11, f1);
    g_wbhi[idx] = make_uint2(h0, h1);
    g_wblo[idx] = make_uint2(bf2_pack(w00 - f0.x, w01 - f0.y),
                             bf2_pack(w10 - f1.x, w11 - f1.y));
}

// ---------------------------------------------------------------------------
// Tensor-core GEMM via baseline mma.sync bf16 split precision:
// xp = x @ W = hi@Whi + hi@Wlo + lo@Whi (fp32 accumulate).
// Split along N: blockIdx.y selects 64 cols (NTB=8 tiles) -> 32 acc regs,
// ~3 resident blocks/SM instead of 2 (the R14 kernel was occupancy/latency
// bound at 22% occ with the 16-tile accumulator file).
// Epilogue stores xp as fp16x2 + per-head logits for this block's 4 heads.
// ---------------------------------------------------------------------------
__global__ __launch_bounds__(256) void gemm_mma(
        const float* __restrict__ x,
        const float* __restrict__ att_src,
        const float* __restrict__ att_dst,
        int n) {
    __shared__ unsigned sXhi[TMR * SXW];   // bf16x2 pairs, [row][k2]
    __shared__ unsigned sXlo[TMR * SXW];
    __shared__ float s_att[256];

    const int tid  = threadIdx.x;
    const int w    = tid >> 5;
    const int lane = tid & 31;
    const int g = lane >> 2, t = lane & 3;
    const int row0 = blockIdx.x * TMR;
    const int colB = blockIdx.y;           // 0 or 1

    {
        const float4* x4 = (const float4*)x;
#pragma unroll
        for (int i = 0; i < 16; i++) {
            int idx = tid + 256 * i;              // 0..4095
            int r  = idx >> 5;
            int c4 = idx & 31;
            float4 v = make_float4(0.f, 0.f, 0.f, 0.f);
            if (row0 + r < n) v = x4[(size_t)(row0 + r) * 32 + c4];
            float2 f01, f23;
            unsigned h01 = bf2_hi(v.x, v.y, f01);
            unsigned h23 = bf2_hi(v.z, v.w, f23);
            *(uint2*)&sXhi[r * SXW + c4 * 2] = make_uint2(h01, h23);
            *(uint2*)&sXlo[r * SXW + c4 * 2] =
                make_uint2(bf2_pack(v.x - f01.x, v.y - f01.y),
                           bf2_pack(v.z - f23.x, v.w - f23.y));
        }
        s_att[tid] = (tid < 128) ? att_src[tid] : att_dst[tid - 128];
    }
    __syncthreads();

    float acc[NTB][4];
#pragma unroll
    for (int nt = 0; nt < NTB; nt++)
#pragma unroll
        for (int j = 0; j < 4; j++) acc[nt][j] = 0.f;

    const int wr = w * 16;
    const int rA = (wr + g) * SXW;
    const int rB = (wr + g + 8) * SXW;
#pragma unroll
    for (int kc = 0; kc < 8; kc++) {
        const int p0 = kc * 8 + t;
        const int p1 = p0 + 4;
        unsigned ahi[4], alo[4];
        ahi[0] = sXhi[rA + p0]; ahi[1] = sXhi[rB + p0];
        ahi[2] = sXhi[rA + p1]; ahi[3] = sXhi[rB + p1];
        alo[0] = sXlo[rA + p0]; alo[1] = sXlo[rB + p0];
        alo[2] = sXlo[rA + p1]; alo[3] = sXlo[rB + p1];

        const uint2* __restrict__ bh = &g_wbhi[kc * 512 + (colB * NTB) * 32 + lane];
        const uint2* __restrict__ bl = &g_wblo[kc * 512 + (colB * NTB) * 32 + lane];
#pragma unroll
        for (int nt = 0; nt < NTB; nt++) {
            uint2 bhv = bh[nt * 32];
            uint2 blv = bl[nt * 32];
            mma16816(acc[nt], ahi, bhv);
            mma16816(acc[nt], alo, bhv);
            mma16816(acc[nt], ahi, blv);
        }
    }

    // Epilogue: rows r0 = row0+wr+g, r1 = r0+8; lane covers global cols
    // colB*64 + nt*8 + 2t, +1 -> fp16x2 word index (colB*8+nt)*4 + t.
    const int r0 = row0 + wr + g;
    const int r1 = r0 + 8;
    const bool ok0 = r0 < n, ok1 = r1 < n;

    float vs0[4], vd0[4], vs1[4], vd1[4];
#pragma unroll
    for (int i = 0; i < 4; i++) { vs0[i] = vd0[i] = vs1[i] = vd1[i] = 0.f; }

#pragma unroll
    for (int nt = 0; nt < NTB; nt++) {
        int c = colB * 64 + nt * 8 + t * 2;       // global col
        int wi = (colB * NTB + nt) * 4 + t;       // fp16x2 word index
        int hh = nt >> 1;                         // local head 0..3
        if (ok0) g_xph[(size_t)r0 * 64 + wi] = h2_pack(acc[nt][0], acc[nt][1]);
        if (ok1) g_xph[(size_t)r1 * 64 + wi] = h2_pack(acc[nt][2], acc[nt][3]);
        float as0 = s_att[c], as1 = s_att[c + 1];
        float ad0 = s_att[128 + c], ad1 = s_att[128 + c + 1];
        vs0[hh] += acc[nt][0] * as0 + acc[nt][1] * as1;
        vd0[hh] += acc[nt][0] * ad0 + acc[nt][1] * ad1;
        vs1[hh] += acc[nt][2] * as0 + acc[nt][3] * as1;
        vd1[hh] += acc[nt][2] * ad0 + acc[nt][3] * ad1;
    }
#pragma unroll
    for (int i = 0; i < 4; i++) {
        vs0[i] += __shfl_xor_sync(0xffffffffu, vs0[i], 1);
        vs0[i] += __shfl_xor_sync(0xffffffffu, vs0[i], 2);
        vd0[i] += __shfl_xor_sync(0xffffffffu, vd0[i], 1);
        vd0[i] += __shfl_xor_sync(0xffffffffu, vd0[i], 2);
        vs1[i] += __shfl_xor_sync(0xffffffffu, vs1[i], 1);
        vs1[i] += __shfl_xor_sync(0xffffffffu, vs1[i], 2);
        vd1[i] += __shfl_xor_sync(0xffffffffu, vd1[i], 1);
        vd1[i] += __shfl_xor_sync(0xffffffffu, vd1[i], 2);
    }
    if (t == 0) {
        const int h0 = colB * 4;                  // this block's first head
        if (ok0) {
#pragma unroll
            for (int i = 0; i < 4; i++) {
                g_asrc[(size_t)r0 * HH + h0 + i] = vs0[i];
                g_adst[(size_t)r0 * HH + h0 + i] = vd0[i];
            }
        }
        if (ok1) {
#pragma unroll
            for (int i = 0; i < 4; i++) {
                g_asrc[(size_t)r1 * HH + h0 + i] = vs1[i];
                g_adst[(size_t)r1 * HH + h0 + i] = vd1[i];
            }
        }
    }
}

// ---------------------------------------------------------------------------
// CSR build
// ---------------------------------------------------------------------------
__global__ void zerocnt_kernel(int n) {
    int i = blockIdx.x * blockDim.x + threadIdx.x;
    if (i <= n) g_cnt[i] = 0;
}

__global__ void hist_kernel(const int* __restrict__ ei, int E) {
    int t = blockIdx.x * blockDim.x + threadIdx.x;
    int e = t * 4;
    if (e + 3 < E) {
        int4 d = *(const int4*)&ei[E + e];
        atomicAdd(&g_cnt[d.x], 1);
        atomicAdd(&g_cnt[d.y], 1);
        atomicAdd(&g_cnt[d.z], 1);
        atomicAdd(&g_cnt[d.w], 1);
    } else {
        for (int k = e; k < E && k < e + 4; k++)
            atomicAdd(&g_cnt[ei[E + k]], 1);
    }
}

__global__ void scan1_kernel(int n) {
    const int i = blockIdx.x * SB + threadIdx.x;
    const int lane = threadIdx.x & 31, wid = threadIdx.x >> 5;
    int v = (i < n) ? g_cnt[i] : 0;
    int x = v;
#pragma unroll
    for (int off = 1; off < 32; off <<= 1) {
        int y = __shfl_up_sync(0xffffffffu, x, off);
        if (lane >= off) x += y;
    }
    __shared__ int ws[32];
    if (lane == 31) ws[wid] = x;
    __syncthreads();
    if (wid == 0) {
        int s = ws[lane];
#pragma unroll
        for (int off = 1; off < 32; off <<= 1) {
            int y = __shfl_up_sync(0xffffffffu, s, off);
            if (lane >= off) s += y;
        }
        ws[lane] = s;
    }
    __syncthreads();
    int excl = x - v + (wid ? ws[wid - 1] : 0);
    if (i <= n) g_rowstart[i] = excl;
    if (threadIdx.x == SB - 1) g_bsum[blockIdx.x] = excl + v;
}

__global__ void scan2_kernel(int nb) {
    const int lane = threadIdx.x;
    int v0 = (lane < nb) ? g_bsum[lane] : 0;
    int v1 = (lane + 32 < nb) ? g_bsum[lane + 32] : 0;
    int x0 = v0;
#pragma unroll
    for (int off = 1; off < 32; off <<= 1) {
        int y = __shfl_up_sync(0xffffffffu, x0, off);
        if (lane >= off) x0 += y;
    }
    int tot0 = __shfl_sync(0xffffffffu, x0, 31);
    int x1 = v1;
#pragma unroll
    for (int off = 1; off < 32; off <<= 1) {
        int y = __shfl_up_sync(0xffffffffu, x1, off);
        if (lane >= off) x1 += y;
    }
    if (lane < nb)      g_bsum[lane]      = x0 - v0;
    if (lane + 32 < nb) g_bsum[lane + 32] = tot0 + x1 - v1;
}

__global__ void scan3_kernel(int n) {
    int i = blockIdx.x * SB + threadIdx.x;
    if (i <= n) {
        int v = g_rowstart[i] + g_bsum[blockIdx.x];
        g_rowstart[i] = v;
        if (i < n) g_cursor[i] = v;
    }
}

__global__ void scatter_kernel(const int* __restrict__ ei, int E) {
    int t = blockIdx.x * blockDim.x + threadIdx.x;
    int e = t * 4;
    if (e + 3 < E) {
        int4 s = *(const int4*)&ei[e];
        int4 d = *(const int4*)&ei[E + e];
        int p0 = atomicAdd(&g_cursor[d.x], 1);
        int p1 = atomicAdd(&g_cursor[d.y], 1);
        int p2 = atomicAdd(&g_cursor[d.z], 1);
        int p3 = atomicAdd(&g_cursor[d.w], 1);
        g_csr[p0] = s.x;
        g_csr[p1] = s.y;
        g_csr[p2] = s.z;
        g_csr[p3] = s.w;
    } else {
        for (int k = e; k < E && k < e + 4; k++) {
            int d = ei[E + k];
            int p = atomicAdd(&g_cursor[d], 1);
            g_csr[p] = ei[k];
        }
    }
}

// ---------------------------------------------------------------------------
// Fused aggregate + softmax-normalize + bias + LayerNorm (R14-proven form:
// 2-way edge unroll, fp16x2 gathers, fp32 accumulation).
// ---------------------------------------------------------------------------
__global__ void agg_kernel(const float* __restrict__ bias,
                           const float* __restrict__ gamma,
                           const float* __restrict__ beta,
                           float* __restrict__ out, int n) {
    const int wrp = (blockIdx.x * blockDim.x + threadIdx.x) >> 5;
    if (wrp >= n) return;
    const int lane = threadIdx.x & 31;
    const int h = lane >> 2;

    const int row = g_rowstart[wrp];
    const int end = g_rowstart[wrp + 1];
    const float adh = g_adst[(size_t)wrp * HH + h];
    const uint2* __restrict__ xph = (const uint2*)g_xph;   // row stride 32

    float4 acc = make_float4(0.f, 0.f, 0.f, 0.f);
    float wsum = 0.f;

    int i = row;
    for (; i + 1 < end; i += 2) {
        int s0 = g_csr[i];
        int s1 = g_csr[i + 1];
        float a0 = g_asrc[(size_t)s0 * HH + h];
        float a1 = g_asrc[(size_t)s1 * HH + h];
        uint2 q0 = xph[(size_t)s0 * 32 + lane];
        uint2 q1 = xph[(size_t)s1 * 32 + lane];
        float v0 = a0 + adh; v0 = v0 > 0.f ? v0 : 0.2f * v0;
        float v1 = a1 + adh; v1 = v1 > 0.f ? v1 : 0.2f * v1;
        float w0 = __expf(v0);
        float w1 = __expf(v1);
        float2 x0a = h2_unpack(q0.x), x0b = h2_unpack(q0.y);
        float2 x1a = h2_unpack(q1.x), x1b = h2_unpack(q1.y);
        acc.x = fmaf(w0, x0a.x, acc.x); acc.y = fmaf(w0, x0a.y, acc.y);
        acc.z = fmaf(w0, x0b.x, acc.z); acc.w = fmaf(w0, x0b.y, acc.w);
        acc.x = fmaf(w1, x1a.x, acc.x); acc.y = fmaf(w1, x1a.y, acc.y);
        acc.z = fmaf(w1, x1b.x, acc.z); acc.w = fmaf(w1, x1b.y, acc.w);
        wsum += w0 + w1;
    }
    if (i < end) {
        int s = g_csr[i];
        float v = g_asrc[(size_t)s * HH + h] + adh;
        v = v > 0.f ? v : 0.2f * v;
        float wgt = __expf(v);
        uint2 q = xph[(size_t)s * 32 + lane];
        float2 xa = h2_unpack(q.x), xb = h2_unpack(q.y);
        acc.x = fmaf(wgt, xa.x, acc.x); acc.y = fmaf(wgt, xa.y, acc.y);
        acc.z = fmaf(wgt, xb.x, acc.z); acc.w = fmaf(wgt, xb.y, acc.w);
        wsum += wgt;
    }
    // self loop
    {
        float v = g_asrc[(size_t)wrp * HH + h] + adh;
        v = v > 0.f ? v : 0.2f * v;
        float wgt = __expf(v);
        uint2 q = xph[(size_t)wrp * 32 + lane];
        float2 xa = h2_unpack(q.x), xb = h2_unpack(q.y);
        acc.x = fmaf(wgt, xa.x, acc.x); acc.y = fmaf(wgt, xa.y, acc.y);
        acc.z = fmaf(wgt, xb.x, acc.z); acc.w = fmaf(wgt, xb.y, acc.w);
        wsum += wgt;
    }

    const float inv_w = 1.f / wsum;
    float4 b4 = ((const float4*)bias)[lane];
    float4 o;
    o.x = acc.x * inv_w + b4.x;
    o.y = acc.y * inv_w + b4.y;
    o.z = acc.z * inv_w + b4.z;
    o.w = acc.w * inv_w + b4.w;

    float s1 = o.x + o.y + o.z + o.w;
    float s2 = o.x * o.x + o.y * o.y + o.z * o.z + o.w * o.w;
#pragma unroll
    for (int off = 16; off; off >>= 1) {
        s1 += __shfl_xor_sync(0xffffffffu, s1, off);
        s2 += __shfl_xor_sync(0xffffffffu, s2, off);
    }
    float mu  = s1 * (1.f / 128.f);
    float var = s2 * (1.f / 128.f) - mu * mu;
    float inv = rsqrtf(var + 1e-5f);

    float4 g4 = ((const float4*)gamma)[lane];
    float4 e4 = ((const float4*)beta)[lane];
    float4 r;
    r.x = (o.x - mu) * inv * g4.x + e4.x;
    r.y = (o.y - mu) * inv * g4.y + e4.y;
    r.z = (o.z - mu) * inv * g4.z + e4.z;
    r.w = (o.w - mu) * inv * g4.w + e4.w;
    ((float4*)out)[(size_t)wrp * 32 + lane] = r;
}

// ---------------------------------------------------------------------------
extern "C" void kernel_launch(void* const* d_in, const int* in_sizes, int n_in,
                              void* d_out, int out_size) {
    const float* x       = (const float*)d_in[0];
    const int*   ei      = (const int*)d_in[1];
    const float* W       = (const float*)d_in[2];
    const float* att_src = (const float*)d_in[3];
    const float* att_dst = (const float*)d_in[4];
    const float* bias    = (const float*)d_in[5];
    const float* gamma   = (const float*)d_in[6];
    const float* beta    = (const float*)d_in[7];
    float* out = (float*)d_out;

    const int n = in_sizes[0] / FD;   // 50000
    const int E = in_sizes[1] / 2;    // 800000
    const int nb = (n + 1 + SB - 1) / SB;

    wfrag_prep<<<16, 256>>>(W);                                       // 0
    zerocnt_kernel<<<(n + 1 + 255) / 256, 256>>>(n);                  // 1
    hist_kernel<<<((E + 3) / 4 + 255) / 256, 256>>>(ei, E);           // 2
    dim3 ggrid((n + TMR - 1) / TMR, 2);
    gemm_mma<<<ggrid, 256>>>(x, att_src, att_dst, n);                 // 3 (profiler slot)
    scan1_kernel<<<nb, SB>>>(n);                                      // 4
    scan2_kernel<<<1, 32>>>(nb);                                      // 5
    scan3_kernel<<<nb, SB>>>(n);                                      // 6
    scatter_kernel<<<((E + 3) / 4 + 255) / 256, 256>>>(ei, E);        // 7
    agg_kernel<<<(n * 32 + 255) / 256, 256>>>(bias, gamma, beta, out, n); // 8
}